// round 1
// baseline (speedup 1.0000x reference)
#include <cuda_runtime.h>
#include <cstdint>

// Problem constants
#define Bn   64
#define Tn   2048
#define Fn   128
#define Hn   512
#define Kn   640          // H + F folded GEMM depth
#define HSn  32           // hidden groups (CTAs per batch group)
#define BSn  4            // batch groups
#define BCn  16           // batches per CTA
#define NTHREADS 256

// SMEM layout (floats)
#define SM_A     0                 // 8*40*32*4 = 40960 permuted tf32 weights
#define SM_HX    40960             // 640 rows * stride 20  = 12800
#define SM_G     (40960+12800)     // gates 64 * stride 17  = 1088
#define SM_BIAS  (SM_G + 64*17)    // 64
#define SM_TOTAL (SM_BIAS + 64)    // 54912 floats = 219648 B
#define HX_STR   20
#define G_STR    17

// Scratch (no cudaMalloc allowed)
__device__ float        g_h[2][Bn * Hn];
__device__ unsigned int g_ctr[BSn];

__device__ __forceinline__ unsigned to_tf32(float f) {
    unsigned u;
    asm("cvt.rna.tf32.f32 %0, %1;" : "=r"(u) : "f"(f));
    return u;
}

__device__ __forceinline__ void mma_tf32(float* c,
                                         unsigned a0, unsigned a1, unsigned a2, unsigned a3,
                                         unsigned b0, unsigned b1) {
    asm volatile(
        "mma.sync.aligned.m16n8k8.row.col.f32.tf32.tf32.f32 "
        "{%0,%1,%2,%3}, {%4,%5,%6,%7}, {%8,%9}, {%0,%1,%2,%3};"
        : "+f"(c[0]), "+f"(c[1]), "+f"(c[2]), "+f"(c[3])
        : "r"(a0), "r"(a1), "r"(a2), "r"(a3), "r"(b0), "r"(b1));
}

__device__ __forceinline__ float sigmoidf_(float x) {
    return 1.f / (1.f + __expf(-x));
}

__global__ void init_ctr_kernel() {
    if (threadIdx.x < BSn) g_ctr[threadIdx.x] = 0u;
}

__global__ void __launch_bounds__(NTHREADS, 1) lstm_persist(
    const float* __restrict__ x,    const float* __restrict__ Wih,
    const float* __restrict__ Whh,  const float* __restrict__ bih,
    const float* __restrict__ bhh,  const float* __restrict__ Wout,
    const float* __restrict__ bout, float* __restrict__ out)
{
    extern __shared__ float sm[];
    float* As  = sm + SM_A;
    float* hxs = sm + SM_HX;
    float* gsm = sm + SM_G;
    float* bsm = sm + SM_BIAS;

    const int tid  = threadIdx.x;
    const int lane = tid & 31;
    const int w    = tid >> 5;            // warp 0..7
    const int q    = blockIdx.x & 31;     // hidden group 0..31
    const int bg   = blockIdx.x >> 5;     // batch group 0..3
    const int b0   = bg * BCn;            // global batch base

    // ---- one-time: permute weights into per-thread mma fragment order (tf32) ----
    // layout: [wk=warp 8][s=kstep 40][lane 32][4 frag regs], warp wk: gate e=wk&3, khalf=wk>>2
    for (int i = tid; i < 8 * 40 * 32 * 4; i += NTHREADS) {
        int j  = i & 3;
        int ln = (i >> 2) & 31;
        int ws = i >> 7;                 // wk*40 + s
        int s  = ws % 40;
        int wk = ws / 40;
        int e  = wk & 3, kh = wk >> 2;
        int arow = (ln >> 2) + ((j & 1) ? 8 : 0);     // row within 16-row tile
        int acol = (ln & 3) + ((j & 2) ? 4 : 0);      // col within k8
        int grow = e * Hn + q * 16 + arow;            // global gate row (i,f,g,o blocks)
        int k    = kh * 320 + s * 8 + acol;
        float v  = (k < Hn) ? Whh[(size_t)grow * Hn + k]
                            : Wih[(size_t)grow * Fn + (k - Hn)];
        As[i] = __uint_as_float(to_tf32(v));
    }
    // bias (b_ih + b_hh), per local gate row
    for (int r = tid; r < 64; r += NTHREADS) {
        int e = r >> 4, ju_ = r & 15;
        int grow = e * Hn + q * 16 + ju_;
        bsm[r] = bih[grow] + bhh[grow];
    }
    // hx: zero h-part (h0 = 0), fill x-part for t=0
    for (int i = tid; i < Hn * HX_STR; i += NTHREADS) hxs[i] = 0.f;
    for (int i = tid; i < BCn * Fn; i += NTHREADS) {
        int b = i >> 7, f = i & 127;
        float v = x[(size_t)(b0 + b) * Tn * Fn + f];
        hxs[(Hn + f) * HX_STR + b] = __uint_as_float(to_tf32(v));
    }

    float creg = 0.f;                     // cell state: this thread owns (bb, ju)
    const int bb = tid >> 4, ju = tid & 15;
    const int e  = w & 3, kh = w >> 2;
    const int kbase = kh * 320;

    for (int t = 0; t < Tn; ++t) {
        __syncthreads();   // hx ready

        // ---- GEMM: gates[64 x 16] += W[64 x 640] * hx[640 x 16] (tf32) ----
        float acc0[4] = {0.f, 0.f, 0.f, 0.f};
        float acc1[4] = {0.f, 0.f, 0.f, 0.f};
        const float4* Ap = reinterpret_cast<const float4*>(As) + (size_t)(w * 40) * 32 + lane;
        const int n0 = lane >> 2;
        #pragma unroll 4
        for (int s = 0; s < 40; ++s) {
            float4 a = Ap[s * 32];
            int k = kbase + s * 8 + (lane & 3);
            const float* hk = hxs + k * HX_STR + n0;
            unsigned b00 = __float_as_uint(hk[0]);
            unsigned b01 = __float_as_uint(hk[4 * HX_STR]);
            unsigned b10 = __float_as_uint(hk[8]);
            unsigned b11 = __float_as_uint(hk[4 * HX_STR + 8]);
            unsigned a0 = __float_as_uint(a.x), a1 = __float_as_uint(a.y);
            unsigned a2 = __float_as_uint(a.z), a3 = __float_as_uint(a.w);
            mma_tf32(acc0, a0, a1, a2, a3, b00, b01);
            mma_tf32(acc1, a0, a1, a2, a3, b10, b11);
        }

        // ---- reduce K-halves + bias into gsm ----
        const int r0 = e * 16 + (lane >> 2);
        const int c0 = (lane & 3) * 2;
        if (kh) {  // K-high warps write partials
            gsm[r0 * G_STR + c0]           = acc0[0];
            gsm[r0 * G_STR + c0 + 1]       = acc0[1];
            gsm[(r0 + 8) * G_STR + c0]     = acc0[2];
            gsm[(r0 + 8) * G_STR + c0 + 1] = acc0[3];
            gsm[r0 * G_STR + 8 + c0]           = acc1[0];
            gsm[r0 * G_STR + 8 + c0 + 1]       = acc1[1];
            gsm[(r0 + 8) * G_STR + 8 + c0]     = acc1[2];
            gsm[(r0 + 8) * G_STR + 8 + c0 + 1] = acc1[3];
        }
        __syncthreads();
        if (!kh) { // K-low warps: final = partial + own acc + bias
            float bi0 = bsm[r0], bi8 = bsm[r0 + 8];
            gsm[r0 * G_STR + c0]           += acc0[0] + bi0;
            gsm[r0 * G_STR + c0 + 1]       += acc0[1] + bi0;
            gsm[(r0 + 8) * G_STR + c0]     += acc0[2] + bi8;
            gsm[(r0 + 8) * G_STR + c0 + 1] += acc0[3] + bi8;
            gsm[r0 * G_STR + 8 + c0]           += acc1[0] + bi0;
            gsm[r0 * G_STR + 8 + c0 + 1]       += acc1[1] + bi0;
            gsm[(r0 + 8) * G_STR + 8 + c0]     += acc1[2] + bi8;
            gsm[(r0 + 8) * G_STR + 8 + c0 + 1] += acc1[3] + bi8;
        }
        __syncthreads();

        // ---- elementwise LSTM cell (thread owns one (batch, unit) pair) ----
        float gi = gsm[(0  + ju) * G_STR + bb];
        float gf = gsm[(16 + ju) * G_STR + bb];
        float gg = gsm[(32 + ju) * G_STR + bb];
        float go = gsm[(48 + ju) * G_STR + bb];
        float iv = sigmoidf_(gi);
        float fv = sigmoidf_(gf);
        float gv = tanhf(gg);
        float ov = sigmoidf_(go);
        creg = fv * creg + iv * gv;
        float hv = ov * tanhf(creg);
        g_h[(t + 1) & 1][(size_t)(b0 + bb) * Hn + q * 16 + ju] = hv;

        // ---- prefetch x for t+1 into hx (mma for t is done) ----
        if (t + 1 < Tn) {
            for (int i = tid; i < BCn * Fn; i += NTHREADS) {
                int b = i >> 7, f = i & 127;
                float v = x[(size_t)(b0 + b) * Tn * Fn + (size_t)(t + 1) * Fn + f];
                hxs[(Hn + f) * HX_STR + b] = __uint_as_float(to_tf32(v));
            }
        }

        // ---- inter-CTA barrier within the batch group (32 CTAs, monotonic counter) ----
        __threadfence();
        __syncthreads();
        if (tid == 0) {
            atomicAdd(&g_ctr[bg], 1u);
            unsigned tgt = (unsigned)HSn * (unsigned)(t + 1);
            while (*((volatile unsigned int*)&g_ctr[bg]) < tgt) { }
            __threadfence();
        }
        __syncthreads();

        // ---- rebuild h-part of hx from double-buffered gmem (L2, bypass L1) ----
        if (t + 1 < Tn) {
            const float* hb = g_h[(t + 1) & 1] + (size_t)b0 * Hn;
            for (int i = tid; i < BCn * (Hn / 4); i += NTHREADS) {
                int b = i >> 7, k4 = i & 127;
                float4 v = __ldcg(reinterpret_cast<const float4*>(hb + (size_t)b * Hn) + k4);
                int kk = k4 * 4;
                hxs[(kk + 0) * HX_STR + b] = __uint_as_float(to_tf32(v.x));
                hxs[(kk + 1) * HX_STR + b] = __uint_as_float(to_tf32(v.y));
                hxs[(kk + 2) * HX_STR + b] = __uint_as_float(to_tf32(v.z));
                hxs[(kk + 3) * HX_STR + b] = __uint_as_float(to_tf32(v.w));
            }
        }
    }

    // ---- final: out[b, o] = relu(h_T) . Wout[o] + bout[o]  (layer 1 is dead code) ----
    if (q == 0 && tid < BCn * 4) {
        int b = tid >> 2, o = tid & 3;
        const float* hb = g_h[0] + (size_t)(b0 + b) * Hn;   // T even -> final h in buffer 0
        const float* wo = Wout + (size_t)o * Hn;
        float sum = bout[o];
        #pragma unroll 8
        for (int j = 0; j < Hn; j += 4) {
            float4 hv = __ldcg(reinterpret_cast<const float4*>(hb + j));
            float4 wv = *reinterpret_cast<const float4*>(wo + j);
            sum += fmaxf(hv.x, 0.f) * wv.x + fmaxf(hv.y, 0.f) * wv.y
                 + fmaxf(hv.z, 0.f) * wv.z + fmaxf(hv.w, 0.f) * wv.w;
        }
        out[(b0 + b) * 4 + o] = sum;
    }
}

extern "C" void kernel_launch(void* const* d_in, const int* in_sizes, int n_in,
                              void* d_out, int out_size) {
    const float* x    = (const float*)d_in[0];
    const float* Wih  = (const float*)d_in[1];
    const float* Whh  = (const float*)d_in[2];
    const float* bih  = (const float*)d_in[3];
    const float* bhh  = (const float*)d_in[4];
    // d_in[5..8]: layer-1 weights — provably unused by the reference output
    const float* Wout = (const float*)d_in[9];
    const float* bout = (const float*)d_in[10];
    float* out = (float*)d_out;

    cudaFuncSetAttribute(lstm_persist, cudaFuncAttributeMaxDynamicSharedMemorySize,
                         SM_TOTAL * (int)sizeof(float));
    init_ctr_kernel<<<1, 32>>>();
    lstm_persist<<<HSn * BSn, NTHREADS, SM_TOTAL * (int)sizeof(float)>>>(
        x, Wih, Whh, bih, bhh, Wout, bout, out);
}

// round 2
// speedup vs baseline: 1.7034x; 1.7034x over previous
#include <cuda_runtime.h>
#include <cstdint>

// Problem constants
#define Bn   64
#define Tn   2048
#define Fn   128
#define Hn   512
#define HSn  32           // hidden groups (CTAs per batch group)
#define BSn  4            // batch groups
#define BCn  16           // batches per CTA
#define NT   256

// SMEM layout (floats)
// hx: packed/swizzled B operand, 80 k8-groups x 128 floats = 10240
//   idx(k,n) = (k>>3)*128 + (k&3)*32 + (((n + 4*(k&3)) & 15)<<1) + ((k>>2)&1)
#define HX_FLOATS   (80*128)
#define GP_RS       18                 // gpart row stride (floats)
#define GP_PER_W    (64*GP_RS)         // 1152
#define GP_FLOATS   (8*GP_PER_W)       // 9216
#define SM_HX   0
#define SM_GP   (SM_HX + HX_FLOATS)
#define SM_BIAS (SM_GP + GP_FLOATS)
#define SM_TOTAL (SM_BIAS + 64)        // 19520 floats = 78080 B

// Scratch (no cudaMalloc allowed)
__device__ float    g_h[2][Bn * Hn];
__device__ unsigned g_ctr[BSn * 32];   // 128B apart per group (no false sharing)

__device__ __forceinline__ unsigned to_tf32(float f) {
    unsigned u;
    asm("cvt.rna.tf32.f32 %0, %1;" : "=r"(u) : "f"(f));
    return u;
}

__device__ __forceinline__ void mma_tf32(float* c,
                                         unsigned a0, unsigned a1, unsigned a2, unsigned a3,
                                         unsigned b0, unsigned b1) {
    asm volatile(
        "mma.sync.aligned.m16n8k8.row.col.f32.tf32.tf32.f32 "
        "{%0,%1,%2,%3}, {%4,%5,%6,%7}, {%8,%9}, {%0,%1,%2,%3};"
        : "+f"(c[0]), "+f"(c[1]), "+f"(c[2]), "+f"(c[3])
        : "r"(a0), "r"(a1), "r"(a2), "r"(a3), "r"(b0), "r"(b1));
}

__device__ __forceinline__ float sigmoidf_(float x) {
    return 1.f / (1.f + __expf(-x));
}

__device__ __forceinline__ int hx_idx(int k, int n) {
    int grp = k >> 3, c = k & 3, hb = (k >> 2) & 1;
    int slot = (n + 4 * c) & 15;
    return grp * 128 + c * 32 + (slot << 1) + hb;
}

__global__ void init_ctr_kernel() {
    if (threadIdx.x < BSn * 32) g_ctr[threadIdx.x] = 0u;
}

__global__ void __launch_bounds__(NT, 1) lstm_persist(
    const float* __restrict__ x,    const float* __restrict__ Wih,
    const float* __restrict__ Whh,  const float* __restrict__ bih,
    const float* __restrict__ bhh,  const float* __restrict__ Wout,
    const float* __restrict__ bout, float* __restrict__ out)
{
    extern __shared__ float sm[];
    float* hxs   = sm + SM_HX;
    float* gpart = sm + SM_GP;
    float* bsm   = sm + SM_BIAS;

    const int tid  = threadIdx.x;
    const int l    = tid & 31;
    const int w    = tid >> 5;            // warp 0..7 => k-slice [w*80, w*80+80)
    const int q    = blockIdx.x & 31;     // hidden group 0..31 (16 units each)
    const int bg   = blockIdx.x >> 5;     // batch group 0..3
    const int b0   = bg * BCn;

    // ---- one-time: load this thread's A fragments (tf32) into registers ----
    // warp w covers ALL 4 gates (M=64) x its K-slice of 80 (10 k8-steps).
    unsigned Ar[10][4][4];
    {
        const int arow0 = l >> 2;
        const int acol0 = l & 3;
        #pragma unroll
        for (int s = 0; s < 10; ++s) {
            #pragma unroll
            for (int g = 0; g < 4; ++g) {
                #pragma unroll
                for (int j = 0; j < 4; ++j) {
                    int arow = arow0 + ((j & 1) << 3);
                    int acol = acol0 + ((j >> 1) << 2);
                    int grow = g * Hn + q * 16 + arow;
                    int k    = w * 80 + s * 8 + acol;
                    float v  = (k < Hn) ? Whh[(size_t)grow * Hn + k]
                                        : Wih[(size_t)grow * Fn + (k - Hn)];
                    Ar[s][g][j] = to_tf32(v);
                }
            }
        }
    }
    // bias (b_ih + b_hh), per local gate row
    if (tid < 64) {
        int e = tid >> 4, r = tid & 15;
        int grow = e * Hn + q * 16 + r;
        bsm[tid] = bih[grow] + bhh[grow];
    }
    // zero hx (h0 = 0), then fill x-part for t=0
    for (int i = tid; i < HX_FLOATS; i += NT) hxs[i] = 0.f;
    __syncthreads();
    {
        const int b  = tid & 15;
        const int f4 = tid >> 4;           // 0..15, two passes below
        #pragma unroll
        for (int jj = 0; jj < 2; ++jj) {
            int ff = (f4 + jj * 16) * 4;   // 0..124 step 4
            float4 v = *reinterpret_cast<const float4*>(
                x + (size_t)(b0 + b) * Tn * Fn + ff);
            hxs[hx_idx(Hn + ff + 0, b)] = __uint_as_float(to_tf32(v.x));
            hxs[hx_idx(Hn + ff + 1, b)] = __uint_as_float(to_tf32(v.y));
            hxs[hx_idx(Hn + ff + 2, b)] = __uint_as_float(to_tf32(v.z));
            hxs[hx_idx(Hn + ff + 3, b)] = __uint_as_float(to_tf32(v.w));
        }
    }

    float creg = 0.f;                      // cell state: thread owns (bb, ju)
    const int bb = tid >> 4, ju = tid & 15;
    unsigned* ctr = &g_ctr[bg * 32];

    const int c_  = l & 3;
    const int n0_ = l >> 2;
    const int slot0 = (n0_ + 4 * c_) & 15;
    const int boff0 = c_ * 32 + (slot0 << 1);
    const int boff1 = c_ * 32 + ((slot0 ^ 8) << 1);

    for (int t = 0; t < Tn; ++t) {
        __syncthreads();   // hx ready

        // ---- GEMM: each warp computes 64x16 partial over its K=80 slice ----
        float acc[4][2][4];
        #pragma unroll
        for (int g = 0; g < 4; ++g)
            #pragma unroll
            for (int h2 = 0; h2 < 2; ++h2)
                #pragma unroll
                for (int j = 0; j < 4; ++j) acc[g][h2][j] = 0.f;

        #pragma unroll
        for (int s = 0; s < 10; ++s) {
            const float* gbase = hxs + (w * 10 + s) * 128;
            float2 bA = *reinterpret_cast<const float2*>(gbase + boff0);
            float2 bB = *reinterpret_cast<const float2*>(gbase + boff1);
            unsigned u0 = __float_as_uint(bA.x), u1 = __float_as_uint(bA.y);
            unsigned u2 = __float_as_uint(bB.x), u3 = __float_as_uint(bB.y);
            #pragma unroll
            for (int g = 0; g < 4; ++g) {
                mma_tf32(acc[g][0], Ar[s][g][0], Ar[s][g][1], Ar[s][g][2], Ar[s][g][3], u0, u1);
                mma_tf32(acc[g][1], Ar[s][g][0], Ar[s][g][1], Ar[s][g][2], Ar[s][g][3], u2, u3);
            }
        }

        // ---- write per-warp partials to smem ----
        {
            int r0 = l >> 2, cc0 = (l & 3) * 2;
            float* gp = gpart + w * GP_PER_W;
            #pragma unroll
            for (int g = 0; g < 4; ++g) {
                #pragma unroll
                for (int h2 = 0; h2 < 2; ++h2) {
                    *reinterpret_cast<float2*>(gp + (g * 16 + r0) * GP_RS + h2 * 8 + cc0) =
                        make_float2(acc[g][h2][0], acc[g][h2][1]);
                    *reinterpret_cast<float2*>(gp + (g * 16 + r0 + 8) * GP_RS + h2 * 8 + cc0) =
                        make_float2(acc[g][h2][2], acc[g][h2][3]);
                }
            }
        }

        // ---- prefetch x(t+1) into REGISTERS (DRAM latency hides under sync+reduce) ----
        float4 xr0, xr1;
        if (t + 1 < Tn) {
            const float* xb = x + (size_t)(b0 + (tid & 15)) * Tn * Fn + (size_t)(t + 1) * Fn;
            xr0 = *reinterpret_cast<const float4*>(xb + (tid >> 4) * 4);
            xr1 = *reinterpret_cast<const float4*>(xb + ((tid >> 4) + 16) * 4);
        }
        __syncthreads();   // partials ready

        // ---- reduce 8 warps + bias, then LSTM cell (thread owns (bb, ju)) ----
        float gate[4];
        #pragma unroll
        for (int g = 0; g < 4; ++g) {
            float sumv = bsm[g * 16 + ju];
            #pragma unroll
            for (int w8 = 0; w8 < 8; ++w8)
                sumv += gpart[w8 * GP_PER_W + (g * 16 + ju) * GP_RS + bb];
            gate[g] = sumv;
        }
        float iv = sigmoidf_(gate[0]);
        float fv = sigmoidf_(gate[1]);
        float gv = tanhf(gate[2]);
        float ov = sigmoidf_(gate[3]);
        creg = fv * creg + iv * gv;
        float hv = ov * tanhf(creg);
        g_h[(t + 1) & 1][(size_t)(b0 + bb) * Hn + q * 16 + ju] = hv;

        // ---- inter-CTA barrier (release/acquire; no heavyweight membar) ----
        __syncthreads();   // all h stores program-ordered before the release below
        if (tid == 0) {
            asm volatile("red.release.gpu.global.add.u32 [%0], %1;"
                         :: "l"(ctr), "r"(1u) : "memory");
            unsigned tgt = (unsigned)HSn * (unsigned)(t + 1), v;
            do {
                asm volatile("ld.acquire.gpu.global.u32 %0, [%1];"
                             : "=r"(v) : "l"(ctr) : "memory");
            } while (v < tgt);
        }
        __syncthreads();

        if (t + 1 < Tn) {
            // ---- rebuild h-part of hx (swizzled, conflict-free STS) ----
            const float* hb = g_h[(t + 1) & 1] + (size_t)b0 * Hn;
            #pragma unroll
            for (int it = 0; it < 8; ++it) {
                int i2 = it * NT + tid;
                int b  = i2 & 15, k4 = i2 >> 4;      // k4: 0..127
                float4 v = __ldcg(reinterpret_cast<const float4*>(hb + (size_t)b * Hn) + k4);
                int k = k4 * 4;
                hxs[hx_idx(k + 0, b)] = __uint_as_float(to_tf32(v.x));
                hxs[hx_idx(k + 1, b)] = __uint_as_float(to_tf32(v.y));
                hxs[hx_idx(k + 2, b)] = __uint_as_float(to_tf32(v.z));
                hxs[hx_idx(k + 3, b)] = __uint_as_float(to_tf32(v.w));
            }
            // ---- store prefetched x(t+1) from registers ----
            {
                int b = tid & 15;
                int ff = (tid >> 4) * 4;
                hxs[hx_idx(Hn + ff + 0, b)] = __uint_as_float(to_tf32(xr0.x));
                hxs[hx_idx(Hn + ff + 1, b)] = __uint_as_float(to_tf32(xr0.y));
                hxs[hx_idx(Hn + ff + 2, b)] = __uint_as_float(to_tf32(xr0.z));
                hxs[hx_idx(Hn + ff + 3, b)] = __uint_as_float(to_tf32(xr0.w));
                int ff2 = ff + 64;
                hxs[hx_idx(Hn + ff2 + 0, b)] = __uint_as_float(to_tf32(xr1.x));
                hxs[hx_idx(Hn + ff2 + 1, b)] = __uint_as_float(to_tf32(xr1.y));
                hxs[hx_idx(Hn + ff2 + 2, b)] = __uint_as_float(to_tf32(xr1.z));
                hxs[hx_idx(Hn + ff2 + 3, b)] = __uint_as_float(to_tf32(xr1.w));
            }
        }
    }

    // ---- final: out[b, o] = relu(h_T) . Wout[o] + bout[o]  (layer 1 is dead code) ----
    if (q == 0 && tid < BCn * 4) {
        int b = tid >> 2, o = tid & 3;
        const float* hb = g_h[0] + (size_t)(b0 + b) * Hn;   // Tn even -> final h in buffer 0
        const float* wo = Wout + (size_t)o * Hn;
        float sum = bout[o];
        #pragma unroll 8
        for (int j = 0; j < Hn; j += 4) {
            float4 hv = __ldcg(reinterpret_cast<const float4*>(hb + j));
            float4 wv = *reinterpret_cast<const float4*>(wo + j);
            sum += fmaxf(hv.x, 0.f) * wv.x + fmaxf(hv.y, 0.f) * wv.y
                 + fmaxf(hv.z, 0.f) * wv.z + fmaxf(hv.w, 0.f) * wv.w;
        }
        out[(b0 + b) * 4 + o] = sum;
    }
}

extern "C" void kernel_launch(void* const* d_in, const int* in_sizes, int n_in,
                              void* d_out, int out_size) {
    const float* x    = (const float*)d_in[0];
    const float* Wih  = (const float*)d_in[1];
    const float* Whh  = (const float*)d_in[2];
    const float* bih  = (const float*)d_in[3];
    const float* bhh  = (const float*)d_in[4];
    // d_in[5..8]: layer-1 weights — provably unused by the reference output
    const float* Wout = (const float*)d_in[9];
    const float* bout = (const float*)d_in[10];
    float* out = (float*)d_out;

    cudaFuncSetAttribute(lstm_persist, cudaFuncAttributeMaxDynamicSharedMemorySize,
                         SM_TOTAL * (int)sizeof(float));
    init_ctr_kernel<<<1, 128>>>();
    lstm_persist<<<HSn * BSn, NT, SM_TOTAL * (int)sizeof(float)>>>(
        x, Wih, Whh, bih, bhh, Wout, bout, out);
}

// round 4
// speedup vs baseline: 2.5140x; 1.4759x over previous
#include <cuda_runtime.h>
#include <cuda_fp16.h>
#include <cstdint>

// Problem constants
#define Bn   64
#define Tn   2048
#define Fn   128
#define Hn   512
#define HSn  32           // hidden groups (CTAs per batch group)
#define BSn  4            // batch groups
#define BCn  16           // batches per CTA
#define NT   256

// hx: fp16 B operand, 40 k16-groups; each group: 16 n * 8 half2-slots, stride 136 (4B units)
// slot(k-pair p, n) = g16*136 + n*8 + ((p&3)*2 | (p>>2)),  g16 = k>>4, p = (k>>1)&7
#define HX_U32      (40*136)           // 5440 u32 (half2 slots + pad)
#define GP_RS       18                 // gpart row stride (floats)
#define GP_PER_W    (64*GP_RS)         // 1152
#define GP_FLOATS   (8*GP_PER_W)       // 9216
#define SM_HX   0
#define SM_GP   (SM_HX + HX_U32)
#define SM_BIAS (SM_GP + GP_FLOATS)
#define SM_TOTAL (SM_BIAS + 64)        // 14720 words = 58880 B

#define FLG_STR 8                      // flags padded 32B apart

// Scratch (no cudaMalloc allowed)
__device__ float    g_h[2][Bn * Hn];
__device__ unsigned g_flag[BSn * HSn * FLG_STR];

__device__ __forceinline__ unsigned h2bits(float a, float b) {
    __half2 h = __floats2half2_rn(a, b);
    return *reinterpret_cast<unsigned*>(&h);
}

__device__ __forceinline__ int hx_slot(int k2 /*pair idx k>>1*/, int n) {
    int g16 = k2 >> 3;
    int p   = k2 & 7;
    int pos = ((p & 3) << 1) | (p >> 2);
    return g16 * 136 + n * 8 + pos;    // u32 units (half2 slots)
}

__device__ __forceinline__ void mma_f16(float* c,
                                        unsigned a0, unsigned a1, unsigned a2, unsigned a3,
                                        unsigned b0, unsigned b1) {
    asm volatile(
        "mma.sync.aligned.m16n8k16.row.col.f32.f16.f16.f32 "
        "{%0,%1,%2,%3}, {%4,%5,%6,%7}, {%8,%9}, {%0,%1,%2,%3};"
        : "+f"(c[0]), "+f"(c[1]), "+f"(c[2]), "+f"(c[3])
        : "r"(a0), "r"(a1), "r"(a2), "r"(a3), "r"(b0), "r"(b1));
}

__device__ __forceinline__ float sigmoidf_(float x) {
    return 1.f / (1.f + __expf(-x));
}
__device__ __forceinline__ float tanh_ap(float x) {
    float y;
    asm("tanh.approx.f32 %0, %1;" : "=f"(y) : "f"(x));
    return y;
}

__global__ void init_flags_kernel() {
    int i = blockIdx.x * blockDim.x + threadIdx.x;
    if (i < BSn * HSn * FLG_STR) g_flag[i] = 0u;
}

__global__ void __launch_bounds__(NT, 1) lstm_persist(
    const float* __restrict__ x,    const float* __restrict__ Wih,
    const float* __restrict__ Whh,  const float* __restrict__ bih,
    const float* __restrict__ bhh,  const float* __restrict__ Wout,
    const float* __restrict__ bout, float* __restrict__ out)
{
    extern __shared__ float sm[];
    unsigned* hxs = reinterpret_cast<unsigned*>(sm + SM_HX);
    float* gpart  = sm + SM_GP;
    float* bsm    = sm + SM_BIAS;

    const int tid  = threadIdx.x;
    const int l    = tid & 31;
    const int w    = tid >> 5;            // warp 0..7 => k-slice [80w, 80w+80)
    const int q    = blockIdx.x & 31;     // hidden group (16 units)
    const int bg   = blockIdx.x >> 5;     // batch group
    const int b0   = bg * BCn;
    unsigned* flg  = g_flag + bg * HSn * FLG_STR;

    // ---- one-time: A fragments (fp16) into registers ----
    // warp w: all 4 gates (M=64) x K-slice 80 = 5 k16-steps; 4 b32 regs per (s,g)
    unsigned Ar[5][4][4];
    {
        const int r0 = l >> 2;
        const int c0 = (l & 3) * 2;
        #pragma unroll
        for (int s = 0; s < 5; ++s)
            #pragma unroll
            for (int g = 0; g < 4; ++g)
                #pragma unroll
                for (int j = 0; j < 4; ++j) {
                    int row = r0 + ((j & 1) << 3);
                    int col = c0 + ((j >> 1) << 3);
                    int grow = g * Hn + q * 16 + row;
                    int k    = w * 80 + s * 16 + col;    // k, k+1 same side of 512
                    float v0, v1;
                    if (k < Hn) {
                        v0 = Whh[(size_t)grow * Hn + k];
                        v1 = Whh[(size_t)grow * Hn + k + 1];
                    } else {
                        v0 = Wih[(size_t)grow * Fn + (k - Hn)];
                        v1 = Wih[(size_t)grow * Fn + (k - Hn) + 1];
                    }
                    Ar[s][g][j] = h2bits(v0, v1);
                }
    }
    if (tid < 64) {
        int e = tid >> 4, r = tid & 15;
        int grow = e * Hn + q * 16 + r;
        bsm[tid] = bih[grow] + bhh[grow];
    }
    // zero hx; fill x(0)
    for (int i = tid; i < HX_U32; i += NT) hxs[i] = 0u;
    __syncthreads();
    {
        int b = tid >> 4, kk = tid & 15;
        #pragma unroll
        for (int jj = 0; jj < 2; ++jj) {
            int k4x = 128 + kk + jj * 16;
            float4 v = *reinterpret_cast<const float4*>(
                x + (size_t)(b0 + b) * Tn * Fn + (k4x - 128) * 4);
            hxs[hx_slot(k4x * 2,     b)] = h2bits(v.x, v.y);
            hxs[hx_slot(k4x * 2 + 1, b)] = h2bits(v.z, v.w);
        }
    }

    float creg = 0.f;                      // cell state: thread owns (bb, ju)
    const int bb = tid >> 4, ju = tid & 15;
    const int n0_   = l >> 2;
    const int boff0 = n0_ * 8 + 2 * (l & 3);
    const int boff1 = (n0_ + 8) * 8 + 2 * (l & 3);

    for (int t = 0; t < Tn; ++t) {
        __syncthreads();   // hx(t) ready

        // ---- GEMM: warp computes 64x16 partial over its K=80 slice (fp16) ----
        float acc[4][2][4];
        #pragma unroll
        for (int g = 0; g < 4; ++g)
            #pragma unroll
            for (int h2 = 0; h2 < 2; ++h2)
                #pragma unroll
                for (int j = 0; j < 4; ++j) acc[g][h2][j] = 0.f;

        #pragma unroll
        for (int s = 0; s < 5; ++s) {
            const unsigned* gb = hxs + (5 * w + s) * 136;
            uint2 v0 = *reinterpret_cast<const uint2*>(gb + boff0);
            uint2 v1 = *reinterpret_cast<const uint2*>(gb + boff1);
            #pragma unroll
            for (int g = 0; g < 4; ++g) {
                mma_f16(acc[g][0], Ar[s][g][0], Ar[s][g][1], Ar[s][g][2], Ar[s][g][3], v0.x, v0.y);
                mma_f16(acc[g][1], Ar[s][g][0], Ar[s][g][1], Ar[s][g][2], Ar[s][g][3], v1.x, v1.y);
            }
        }

        // ---- write per-warp partials ----
        {
            int r0 = l >> 2, cc0 = (l & 3) * 2;
            float* gp = gpart + w * GP_PER_W;
            #pragma unroll
            for (int g = 0; g < 4; ++g)
                #pragma unroll
                for (int h2 = 0; h2 < 2; ++h2) {
                    *reinterpret_cast<float2*>(gp + (g * 16 + r0) * GP_RS + h2 * 8 + cc0) =
                        make_float2(acc[g][h2][0], acc[g][h2][1]);
                    *reinterpret_cast<float2*>(gp + (g * 16 + r0 + 8) * GP_RS + h2 * 8 + cc0) =
                        make_float2(acc[g][h2][2], acc[g][h2][3]);
                }
        }
        __syncthreads();   // S1: partials ready

        // ---- prefetch x(t+1) into registers ----
        float4 xr0, xr1;
        if (t + 1 < Tn) {
            const float* xb = x + (size_t)(b0 + (tid >> 4)) * Tn * Fn + (size_t)(t + 1) * Fn;
            xr0 = *reinterpret_cast<const float4*>(xb + (tid & 15) * 4);
            xr1 = *reinterpret_cast<const float4*>(xb + ((tid & 15) + 16) * 4);
        }

        // ---- reduce 8 partials (tree) + bias, LSTM cell ----
        float gate[4];
        #pragma unroll
        for (int g = 0; g < 4; ++g) {
            int row = g * 16 + ju;
            float p0 = gpart[0 * GP_PER_W + row * GP_RS + bb];
            float p1 = gpart[1 * GP_PER_W + row * GP_RS + bb];
            float p2 = gpart[2 * GP_PER_W + row * GP_RS + bb];
            float p3 = gpart[3 * GP_PER_W + row * GP_RS + bb];
            float p4 = gpart[4 * GP_PER_W + row * GP_RS + bb];
            float p5 = gpart[5 * GP_PER_W + row * GP_RS + bb];
            float p6 = gpart[6 * GP_PER_W + row * GP_RS + bb];
            float p7 = gpart[7 * GP_PER_W + row * GP_RS + bb];
            gate[g] = bsm[row] + (((p0 + p1) + (p2 + p3)) + ((p4 + p5) + (p6 + p7)));
        }
        float iv = sigmoidf_(gate[0]);
        float fv = sigmoidf_(gate[1]);
        float gv = tanh_ap(gate[2]);
        float ov = sigmoidf_(gate[3]);
        creg = fv * creg + iv * gv;
        float hv = ov * tanh_ap(creg);
        g_h[(t + 1) & 1][(size_t)(b0 + bb) * Hn + q * 16 + ju] = hv;
        // own chunk straight into smem (group g16 == q)
        {
            int k = q * 16 + ju;
            reinterpret_cast<__half*>(hxs)[hx_slot(k >> 1, bb) * 2 + (k & 1)] = __float2half_rn(hv);
        }
        __syncthreads();   // S2: all h stores done

        if (tid == 0) {
            asm volatile("st.release.gpu.global.u32 [%0], %1;"
                         :: "l"(flg + q * FLG_STR), "r"((unsigned)(t + 1)) : "memory");
        }

        if (t + 1 < Tn) {
            // ---- distributed poll: warp w needs producers 4w..4w+3 ----
            const unsigned tgt = (unsigned)(t + 1);
            const int qq = 4 * w + (l & 3);
            bool need = (l < 4) && (qq != q);
            bool ok = !need;
            for (;;) {
                if (!ok) {
                    unsigned vv;
                    asm volatile("ld.acquire.gpu.global.u32 %0, [%1];"
                                 : "=r"(vv) : "l"(flg + qq * FLG_STR) : "memory");
                    ok = vv >= tgt;
                }
                if (__all_sync(0xffffffffu, ok)) break;
                __nanosleep(32);
            }
            // ---- rebuild h-part for this warp's K-slice ----
            const float* hb = g_h[(t + 1) & 1] + (size_t)b0 * Hn;
            const int k4 = 16 * w + (l & 15);
            const int bh = l >> 4;
            if ((k4 >> 2) != q) {
                #pragma unroll
                for (int j = 0; j < 8; ++j) {
                    int b = 2 * j + bh;
                    float4 v = __ldcg(reinterpret_cast<const float4*>(hb + (size_t)b * Hn) + k4);
                    hxs[hx_slot(k4 * 2,     b)] = h2bits(v.x, v.y);
                    hxs[hx_slot(k4 * 2 + 1, b)] = h2bits(v.z, v.w);
                }
            }
            // ---- x(t+1) from prefetched regs ----
            {
                int b = tid >> 4, kk = tid & 15;
                int k4x = 128 + kk;
                hxs[hx_slot(k4x * 2,     b)] = h2bits(xr0.x, xr0.y);
                hxs[hx_slot(k4x * 2 + 1, b)] = h2bits(xr0.z, xr0.w);
                k4x += 16;
                hxs[hx_slot(k4x * 2,     b)] = h2bits(xr1.x, xr1.y);
                hxs[hx_slot(k4x * 2 + 1, b)] = h2bits(xr1.z, xr1.w);
            }
        }
    }

    // ---- final: out[b, o] = relu(h_T) . Wout[o] + bout[o] (layer 1 is dead code) ----
    if (q == 0) {
        if (tid < HSn) {
            for (;;) {
                unsigned vv;
                asm volatile("ld.acquire.gpu.global.u32 %0, [%1];"
                             : "=r"(vv) : "l"(flg + tid * FLG_STR) : "memory");
                if (vv >= (unsigned)Tn) break;
                __nanosleep(64);
            }
        }
        __syncthreads();
        if (tid < BCn * 4) {
            int b = tid >> 2, o = tid & 3;
            const float* hb = g_h[0] + (size_t)(b0 + b) * Hn;   // Tn even
            const float* wo = Wout + (size_t)o * Hn;
            float sum = bout[o];
            #pragma unroll 8
            for (int j = 0; j < Hn; j += 4) {
                float4 hv = __ldcg(reinterpret_cast<const float4*>(hb + j));
                float4 wv = *reinterpret_cast<const float4*>(wo + j);
                sum += fmaxf(hv.x, 0.f) * wv.x + fmaxf(hv.y, 0.f) * wv.y
                     + fmaxf(hv.z, 0.f) * wv.z + fmaxf(hv.w, 0.f) * wv.w;
            }
            out[(b0 + b) * 4 + o] = sum;
        }
    }
}

extern "C" void kernel_launch(void* const* d_in, const int* in_sizes, int n_in,
                              void* d_out, int out_size) {
    const float* x    = (const float*)d_in[0];
    const float* Wih  = (const float*)d_in[1];
    const float* Whh  = (const float*)d_in[2];
    const float* bih  = (const float*)d_in[3];
    const float* bhh  = (const float*)d_in[4];
    // d_in[5..8]: layer-1 weights — provably unused by the reference output
    const float* Wout = (const float*)d_in[9];
    const float* bout = (const float*)d_in[10];
    float* out = (float*)d_out;

    cudaFuncSetAttribute(lstm_persist, cudaFuncAttributeMaxDynamicSharedMemorySize,
                         SM_TOTAL * (int)sizeof(float));
    init_flags_kernel<<<2, 512>>>();
    lstm_persist<<<HSn * BSn, NT, SM_TOTAL * (int)sizeof(float)>>>(
        x, Wih, Whh, bih, bhh, Wout, bout, out);
}